// round 16
// baseline (speedup 1.0000x reference)
#include <cuda_runtime.h>
#include <cuda_bf16.h>
#include <cstdint>
#include <cstddef>

#define B_ 4
#define L_ 512
#define HID_ 512
#define H_ 8
#define DH_ 64

// ---------------- scratch (device globals; no allocations allowed) ----------
__device__ float g_sc[B_ * H_ * L_ * L_];            // qk scores (fp32)
__device__ __nv_bfloat16 g_Xs[2048 * 1536];          // proj A split
__device__ __nv_bfloat16 g_Ws[3 * 512 * 1536];       // proj B split
__device__ __nv_bfloat16 g_qs[32 * 512 * 128];       // q split [bh][l][qh|ql]
__device__ __nv_bfloat16 g_ks[32 * 512 * 128];       // k split [bh][l][kh|kl]
__device__ __nv_bfloat16 g_ps[32 * 512 * 1024];      // probs split [bh][q][ph|pl]
__device__ __nv_bfloat16 g_vT[32 * 64 * 1024];       // v^T split [bh][d][vh|vl]

// ---------------- cp.async helpers ------------------------------------------
__device__ __forceinline__ void cp_async16(void* smem, const void* gmem) {
    unsigned s = (unsigned)__cvta_generic_to_shared(smem);
    asm volatile("cp.async.cg.shared.global [%0], [%1], 16;\n" :: "r"(s), "l"(gmem));
}
__device__ __forceinline__ void cp_commit() {
    asm volatile("cp.async.commit_group;\n");
}
template <int N>
__device__ __forceinline__ void cp_wait() {
    asm volatile("cp.async.wait_group %0;\n" :: "n"(N));
}

// ---------------- warp mma / ldmatrix (sm_80+, no 'a' feature) ---------------
__device__ __forceinline__ void mma_bf16(float& c0, float& c1, float& c2, float& c3,
                                         uint32_t a0, uint32_t a1, uint32_t a2, uint32_t a3,
                                         uint32_t b0, uint32_t b1) {
    asm volatile(
        "mma.sync.aligned.m16n8k16.row.col.f32.bf16.bf16.f32 "
        "{%0,%1,%2,%3}, {%4,%5,%6,%7}, {%8,%9}, {%0,%1,%2,%3};"
        : "+f"(c0), "+f"(c1), "+f"(c2), "+f"(c3)
        : "r"(a0), "r"(a1), "r"(a2), "r"(a3), "r"(b0), "r"(b1));
}
__device__ __forceinline__ void ldm_x4(uint32_t* r, uint32_t addr) {
    asm volatile("ldmatrix.sync.aligned.m8n8.x4.shared.b16 {%0,%1,%2,%3}, [%4];"
                 : "=r"(r[0]), "=r"(r[1]), "=r"(r[2]), "=r"(r[3]) : "r"(addr));
}
__device__ __forceinline__ void ldm_x2(uint32_t& r0, uint32_t& r1, uint32_t addr) {
    asm volatile("ldmatrix.sync.aligned.m8n8.x2.shared.b16 {%0,%1}, [%2];"
                 : "=r"(r0), "=r"(r1) : "r"(addr));
}
__device__ __forceinline__ void ldm_x2_trans(uint32_t& r0, uint32_t& r1, uint32_t addr) {
    asm volatile("ldmatrix.sync.aligned.m8n8.x2.trans.shared.b16 {%0,%1}, [%2];"
                 : "=r"(r0), "=r"(r1) : "r"(addr));
}
__device__ __forceinline__ uint32_t cvt_bf16x2(float a, float b) {
    uint32_t w;
    asm("cvt.rn.bf16x2.f32 %0, %1, %2;" : "=r"(w) : "f"(b), "f"(a));
    return w;
}

// =============================================================================
// K0: build split-bf16 operands for the projection, K=1536.
// =============================================================================
__global__ __launch_bounds__(256) void k_prep(
    const float* __restrict__ X,
    const float* __restrict__ Wq, const float* __restrict__ Wk,
    const float* __restrict__ Wv)
{
    const int stride = gridDim.x * blockDim.x;
    for (int i = blockIdx.x * blockDim.x + threadIdx.x; i < 2048 * 512; i += stride) {
        int m = i >> 9, k = i & 511;
        float x = X[i];
        __nv_bfloat16 hi = __float2bfloat16(x);
        __nv_bfloat16 lo = __float2bfloat16(x - __bfloat162float(hi));
        __nv_bfloat16* row = g_Xs + (size_t)m * 1536;
        row[k] = hi; row[512 + k] = lo; row[1024 + k] = hi;
    }
    for (int i = blockIdx.x * blockDim.x + threadIdx.x; i < 3 * 512 * 512; i += stride) {
        int z = i >> 18;
        int r = i & 262143;
        const float* W = (z == 0) ? Wq : (z == 1) ? Wk : Wv;
        int n = r >> 9, k = r & 511;
        float x = W[r];
        __nv_bfloat16 hi = __float2bfloat16(x);
        __nv_bfloat16 lo = __float2bfloat16(x - __bfloat162float(hi));
        __nv_bfloat16* row = g_Ws + (size_t)z * 512 * 1536 + (size_t)n * 1536;
        row[k] = hi; row[512 + k] = hi; row[1024 + k] = lo;
    }
}

// =============================================================================
// K1: QKV projection via mma.sync (unchanged from R15).
// =============================================================================
#define PADK 72
#define A_BUF_ELE (128 * PADK)
#define B_BUF_ELE (64 * PADK)
#define SMEM_PROJ ((2 * A_BUF_ELE + 2 * B_BUF_ELE) * 2 + 64 * 4)

__global__ __launch_bounds__(256) void k_proj_mma(
    const float* __restrict__ bq, const float* __restrict__ bk,
    const float* __restrict__ bv)
{
    extern __shared__ char smp[];
    __nv_bfloat16* As = (__nv_bfloat16*)smp;
    __nv_bfloat16* Bs = As + 2 * A_BUF_ELE;
    float* biasS = (float*)(Bs + 2 * B_BUF_ELE);

    const int n0 = blockIdx.x * 64;
    const int m0 = blockIdx.y * 128;
    const int z  = blockIdx.z;
    const float* bias = (z == 0) ? bq : (z == 1) ? bk : bv;
    const __nv_bfloat16* Wz = g_Ws + (size_t)z * 512 * 1536;

    const int tid = threadIdx.x;
    const int wid = tid >> 5, lane = tid & 31;
    const int wm = wid >> 1, wn = wid & 1;
    const int g  = lane >> 2, tg = lane & 3;

    if (tid < 64) biasS[tid] = bias[n0 + tid];

    float acc[2][4][4];
#pragma unroll
    for (int mt = 0; mt < 2; mt++)
#pragma unroll
        for (int nt = 0; nt < 4; nt++)
#pragma unroll
            for (int e = 0; e < 4; e++) acc[mt][nt][e] = 0.f;

    auto load_chunk = [&](int c, int buf) {
        __nv_bfloat16* Ad = As + buf * A_BUF_ELE;
        __nv_bfloat16* Bd = Bs + buf * B_BUF_ELE;
#pragma unroll
        for (int i = 0; i < 4; i++) {
            int flat = i * 256 + tid;
            int row = flat >> 3, seg = flat & 7;
            cp_async16(Ad + row * PADK + seg * 8,
                       g_Xs + (size_t)(m0 + row) * 1536 + c * 64 + seg * 8);
        }
#pragma unroll
        for (int i = 0; i < 2; i++) {
            int flat = i * 256 + tid;
            int row = flat >> 3, seg = flat & 7;
            cp_async16(Bd + row * PADK + seg * 8,
                       Wz + (size_t)(n0 + row) * 1536 + c * 64 + seg * 8);
        }
        cp_commit();
    };

    load_chunk(0, 0);

#pragma unroll 1
    for (int t = 0; t < 24; t++) {
        if (t < 23) load_chunk(t + 1, (t + 1) & 1);
        if (t < 23) cp_wait<1>(); else cp_wait<0>();
        __syncthreads();

        const __nv_bfloat16* Ab = As + (t & 1) * A_BUF_ELE;
        const __nv_bfloat16* Bb = Bs + (t & 1) * B_BUF_ELE;

#pragma unroll
        for (int ks = 0; ks < 4; ks++) {
            const int kb = ks * 16;
            uint32_t af[2][4], bf[4][2];
#pragma unroll
            for (int mt = 0; mt < 2; mt++) {
                int r0 = wm * 32 + mt * 16 + g;
                af[mt][0] = *(const uint32_t*)&Ab[(r0)      * PADK + kb + tg * 2];
                af[mt][1] = *(const uint32_t*)&Ab[(r0 + 8)  * PADK + kb + tg * 2];
                af[mt][2] = *(const uint32_t*)&Ab[(r0)      * PADK + kb + tg * 2 + 8];
                af[mt][3] = *(const uint32_t*)&Ab[(r0 + 8)  * PADK + kb + tg * 2 + 8];
            }
#pragma unroll
            for (int nt = 0; nt < 4; nt++) {
                int nr = wn * 32 + nt * 8 + g;
                bf[nt][0] = *(const uint32_t*)&Bb[nr * PADK + kb + tg * 2];
                bf[nt][1] = *(const uint32_t*)&Bb[nr * PADK + kb + tg * 2 + 8];
            }
#pragma unroll
            for (int mt = 0; mt < 2; mt++)
#pragma unroll
                for (int nt = 0; nt < 4; nt++)
                    mma_bf16(acc[mt][nt][0], acc[mt][nt][1], acc[mt][nt][2], acc[mt][nt][3],
                             af[mt][0], af[mt][1], af[mt][2], af[mt][3],
                             bf[nt][0], bf[nt][1]);
        }
        __syncthreads();
    }

    const int hh = n0 >> 6;

    if (z == 2) {
        float* vts = (float*)smp;
#pragma unroll
        for (int mt = 0; mt < 2; mt++) {
            int rl = wm * 32 + mt * 16 + g;
#pragma unroll
            for (int nt = 0; nt < 4; nt++) {
                int cl = wn * 32 + nt * 8 + tg * 2;
                vts[rl * 68 + cl]           = acc[mt][nt][0] + biasS[cl];
                vts[rl * 68 + cl + 1]       = acc[mt][nt][1] + biasS[cl + 1];
                vts[(rl + 8) * 68 + cl]     = acc[mt][nt][2] + biasS[cl];
                vts[(rl + 8) * 68 + cl + 1] = acc[mt][nt][3] + biasS[cl + 1];
            }
        }
        __syncthreads();
        const int d = tid & 63, ksb = tid >> 6;
        const int bh = (m0 >> 9) * 8 + hh;
        const int l0 = (m0 & 511) + ksb * 32;
        __nv_bfloat16* dst = g_vT + ((size_t)bh * 64 + d) * 1024 + l0;
#pragma unroll
        for (int seg = 0; seg < 4; seg++) {
            union { __nv_bfloat16 bb[8]; uint4 u; } hu, lu;
#pragma unroll
            for (int j = 0; j < 8; j++) {
                float x = vts[(ksb * 32 + seg * 8 + j) * 68 + d];
                __nv_bfloat16 hb = __float2bfloat16(x);
                hu.bb[j] = hb;
                lu.bb[j] = __float2bfloat16(x - __bfloat162float(hb));
            }
            *(uint4*)(dst + seg * 8)       = hu.u;
            *(uint4*)(dst + 512 + seg * 8) = lu.u;
        }
    } else {
        __nv_bfloat16* QK = (z == 0) ? g_qs : g_ks;
#pragma unroll
        for (int mt = 0; mt < 2; mt++) {
            int r0 = m0 + wm * 32 + mt * 16 + g;
#pragma unroll
            for (int nt = 0; nt < 4; nt++) {
                int cl = wn * 32 + nt * 8 + tg * 2;
                float x00 = acc[mt][nt][0] + biasS[cl];
                float x01 = acc[mt][nt][1] + biasS[cl + 1];
                float x10 = acc[mt][nt][2] + biasS[cl];
                float x11 = acc[mt][nt][3] + biasS[cl + 1];
                int b0 = r0 >> 9, l0 = r0 & 511;
                int b1 = (r0 + 8) >> 9, l1 = (r0 + 8) & 511;
                __nv_bfloat16* d0 = QK + ((size_t)(b0 * 8 + hh) * 512 + l0) * 128 + cl;
                __nv_bfloat16* d1 = QK + ((size_t)(b1 * 8 + hh) * 512 + l1) * 128 + cl;
                __nv_bfloat16 h00 = __float2bfloat16(x00), h01 = __float2bfloat16(x01);
                __nv_bfloat16 h10 = __float2bfloat16(x10), h11 = __float2bfloat16(x11);
                *(uint32_t*)d0 = ((uint32_t)__bfloat16_as_ushort(h01) << 16)
                               | __bfloat16_as_ushort(h00);
                *(uint32_t*)d1 = ((uint32_t)__bfloat16_as_ushort(h11) << 16)
                               | __bfloat16_as_ushort(h10);
                *(uint32_t*)(d0 + 64) = cvt_bf16x2(x00 - __bfloat162float(h00),
                                                   x01 - __bfloat162float(h01));
                *(uint32_t*)(d1 + 64) = cvt_bf16x2(x10 - __bfloat162float(h10),
                                                   x11 - __bfloat162float(h11));
            }
        }
    }
}

// =============================================================================
// K2: scores via mma.sync, single-phase (unchanged from R15).
// =============================================================================
#define SC_TILE (128 * PADK)
#define SMEM_SC2 (6 * SC_TILE * 2)

__global__ __launch_bounds__(256) void k_scores_mma()
{
    extern __shared__ char smp[];
    __nv_bfloat16* As = (__nv_bfloat16*)smp;
    __nv_bfloat16* Bs = As + 3 * SC_TILE;

    const int n0 = blockIdx.x * 128;
    const int m0 = blockIdx.y * 128;
    const int bh = blockIdx.z;
    const __nv_bfloat16* Aq = g_qs + (size_t)bh * 512 * 128;
    const __nv_bfloat16* Bk = g_ks + (size_t)bh * 512 * 128;
    float* C = g_sc + (size_t)bh * 262144;

    const int tid = threadIdx.x;
    const int wid = tid >> 5, lane = tid & 31;
    const int wm = wid >> 1, wn = wid & 1;
    const int g  = lane >> 2, tg = lane & 3;

    const int Aoff[3] = { 0, 64, 0 };
    const int Boff[3] = { 0, 0, 64 };

#pragma unroll
    for (int c = 0; c < 3; c++) {
#pragma unroll
        for (int i = 0; i < 4; i++) {
            int flat = i * 256 + tid;
            int row = flat >> 3, seg = flat & 7;
            cp_async16(As + c * SC_TILE + row * PADK + seg * 8,
                       Aq + (size_t)(m0 + row) * 128 + Aoff[c] + seg * 8);
        }
#pragma unroll
        for (int i = 0; i < 4; i++) {
            int flat = i * 256 + tid;
            int row = flat >> 3, seg = flat & 7;
            cp_async16(Bs + c * SC_TILE + row * PADK + seg * 8,
                       Bk + (size_t)(n0 + row) * 128 + Boff[c] + seg * 8);
        }
    }
    cp_commit();
    cp_wait<0>();
    __syncthreads();

    float acc[2][8][4];
#pragma unroll
    for (int mt = 0; mt < 2; mt++)
#pragma unroll
        for (int nt = 0; nt < 8; nt++)
#pragma unroll
            for (int e = 0; e < 4; e++) acc[mt][nt][e] = 0.f;

#pragma unroll
    for (int c = 0; c < 3; c++) {
        const __nv_bfloat16* Ab = As + c * SC_TILE;
        const __nv_bfloat16* Bb = Bs + c * SC_TILE;
#pragma unroll
        for (int ks = 0; ks < 4; ks++) {
            const int kb = ks * 16;
            uint32_t af[2][4], bf[8][2];
#pragma unroll
            for (int mt = 0; mt < 2; mt++) {
                int r0 = wm * 32 + mt * 16 + g;
                af[mt][0] = *(const uint32_t*)&Ab[(r0)      * PADK + kb + tg * 2];
                af[mt][1] = *(const uint32_t*)&Ab[(r0 + 8)  * PADK + kb + tg * 2];
                af[mt][2] = *(const uint32_t*)&Ab[(r0)      * PADK + kb + tg * 2 + 8];
                af[mt][3] = *(const uint32_t*)&Ab[(r0 + 8)  * PADK + kb + tg * 2 + 8];
            }
#pragma unroll
            for (int nt = 0; nt < 8; nt++) {
                int nr = wn * 64 + nt * 8 + g;
                bf[nt][0] = *(const uint32_t*)&Bb[nr * PADK + kb + tg * 2];
                bf[nt][1] = *(const uint32_t*)&Bb[nr * PADK + kb + tg * 2 + 8];
            }
#pragma unroll
            for (int mt = 0; mt < 2; mt++)
#pragma unroll
                for (int nt = 0; nt < 8; nt++)
                    mma_bf16(acc[mt][nt][0], acc[mt][nt][1], acc[mt][nt][2], acc[mt][nt][3],
                             af[mt][0], af[mt][1], af[mt][2], af[mt][3],
                             bf[nt][0], bf[nt][1]);
        }
    }

#pragma unroll
    for (int mt = 0; mt < 2; mt++) {
        int r0 = m0 + wm * 32 + mt * 16 + g;
#pragma unroll
        for (int nt = 0; nt < 8; nt++) {
            int cl = wn * 64 + nt * 8 + tg * 2;
            *(float2*)&C[(size_t)r0 * 512 + n0 + cl] =
                make_float2(acc[mt][nt][0], acc[mt][nt][1]);
            *(float2*)&C[(size_t)(r0 + 8) * 512 + n0 + cl] =
                make_float2(acc[mt][nt][2], acc[mt][nt][3]);
        }
    }
}

// =============================================================================
// K3: fused per-(b,q) — FLASH-CHUNKED (2 chunks of 256 rels rows, online
// softmax, register-resident ctx accumulators).  smem 111KB -> 2 CTAs/SM.
// =============================================================================
#define F_RH 0                       // 256 x 128B = 32768
#define F_RL 32768                   // 32768
#define F_SC 65536                   // float [8][260] = 8320
#define F_QS 73856                   // bf16 [16][136] = 4352
#define F_PS 78208                   // bf16 [16][520] = 16640
#define F_RED 94848                  // float2 [64][32] = 16384
#define F_MS 111232                  // msm/ssm/fsm/ism [8] each = 128
#define SMEM_FUSED 111360

__global__ __launch_bounds__(512, 2) void k_fused(
    const float* __restrict__ rels,
    const float* __restrict__ heads,
    float* __restrict__ out)
{
    extern __shared__ char smf[];
    const uint32_t sbase = (uint32_t)__cvta_generic_to_shared(smf);
    float* sc_s = (float*)(smf + F_SC);
    __nv_bfloat16* QS = (__nv_bfloat16*)(smf + F_QS);
    __nv_bfloat16* PS = (__nv_bfloat16*)(smf + F_PS);
    float* red = (float*)(smf + F_RED);
    float* msm = (float*)(smf + F_MS);
    float* ssm = msm + 8;
    float* fsm = msm + 16;
    float* ism = msm + 24;

    const int bq = blockIdx.x;
    const int b = bq >> 9, q = bq & 511;
    const int tid = threadIdx.x;
    const int lane = tid & 31, w = tid >> 5;

    const float* rg = rels + (size_t)bq * (512 * 64);
    const size_t hoff = ((size_t)b * 512 + q) * 512;

    // ---- prologue: QS build + chunk0 LDG ----
    if (tid < 128) {
        int h = tid >> 4, dq = tid & 15;
        const __nv_bfloat16* src = g_qs + ((size_t)(b * 8 + h) * 512 + q) * 128 + dq * 4;
        *(uint2*)&QS[h * 136 + dq * 4]       = *(const uint2*)src;
        *(uint2*)&QS[(h + 8) * 136 + dq * 4] = *(const uint2*)(src + 64);
    }

    float4 stg[8];
    {
        int rr = tid >> 1, f0 = (tid & 1) * 8;
        const float4* src = (const float4*)(rg + (size_t)rr * 64) + f0;
#pragma unroll
        for (int j = 0; j < 8; j++) stg[j] = src[j];
    }
    __syncthreads();

    uint32_t afr[4][4];
#pragma unroll
    for (int ds = 0; ds < 4; ds++) {
        uint32_t addr = sbase + F_QS + (lane & 15) * 272
                      + (ds * 16 + ((lane >> 4) << 3)) * 2;
        ldm_x4(afr[ds], addr);
    }

    float aD[4][4];
#pragma unroll
    for (int i = 0; i < 4; i++)
#pragma unroll
        for (int j = 0; j < 4; j++) aD[i][j] = 0.f;
    const int kg = w >> 1, ng = w & 1;

#pragma unroll 1
    for (int c = 0; c < 2; c++) {
        // qk/heads prefetch for this chunk (2 tiles per warp)
        float2 qkP[2], hvP[2];
        {
            int hh = lane >> 2;
#pragma unroll
            for (int half = 0; half < 2; half++) {
                int kkg = c * 256 + (w * 2 + half) * 8 + (lane & 3) * 2;
                qkP[half] = *(const float2*)&g_sc[(size_t)(b * 8 + hh) * 262144
                                                  + (size_t)q * 512 + kkg];
                hvP[half] = *(const float2*)&heads[hoff + kkg];
            }
        }

        // ---- STS chunk (stg regs -> smem, swizzled), local rows 0..255 ----
        {
            int rr = tid >> 1;
            int c0 = (tid & 1) * 4;
            char* rhrow = smf + F_RH + rr * 128;
            char* rlrow = smf + F_RL + rr * 128;
            int s7 = rr & 7;
#pragma unroll
            for (int jj = 0; jj < 4; jj++) {
                const float* xs = (const float*)&stg[jj * 2];
                uint32_t hw[4], lw[4];
#pragma unroll
                for (int j = 0; j < 4; j++) {
                    float x0 = xs[2 * j], x1 = xs[2 * j + 1];
                    uint32_t u0 = __float_as_uint(x0), u1 = __float_as_uint(x1);
                    hw[j] = __byte_perm(u0, u1, 0x7632);
                    float h0f = __uint_as_float(u0 & 0xFFFF0000u);
                    float h1f = __uint_as_float(u1 & 0xFFFF0000u);
                    lw[j] = cvt_bf16x2(x0 - h0f, x1 - h1f);
                }
                int chunk = c0 + jj;
                *(uint4*)(rhrow + ((chunk ^ s7) << 4)) = make_uint4(hw[0], hw[1], hw[2], hw[3]);
                *(uint4*)(rlrow + ((chunk ^ s7) << 4)) = make_uint4(lw[0], lw[1], lw[2], lw[3]);
            }
        }
        __syncthreads();   // rels chunk c ready

        // ---- stage B: all 16 warps, 2 n-tiles each (local k 0..255) ----
#pragma unroll
        for (int half = 0; half < 2; half++) {
            const int k0l = (w * 2 + half) * 8;
            float p0c0 = 0.f, p0c1 = 0.f, p0c2 = 0.f, p0c3 = 0.f;
            float p1c0 = 0.f, p1c1 = 0.f, p1c2 = 0.f, p1c3 = 0.f;
            const int row = k0l + (lane & 7);
            const int s7 = row & 7;
            const int csel = (lane >> 3) & 1;
#pragma unroll
            for (int ds = 0; ds < 4; ds++) {
                int chunk = ds * 2 + csel;
                uint32_t b0, b1;
                ldm_x2(b0, b1, sbase + F_RH + row * 128 + ((chunk ^ s7) << 4));
                mma_bf16(p0c0, p0c1, p0c2, p0c3,
                         afr[ds][0], afr[ds][1], afr[ds][2], afr[ds][3], b0, b1);
            }
#pragma unroll
            for (int ds = 0; ds < 4; ds++) {
                int chunk = ds * 2 + csel;
                uint32_t b0, b1;
                ldm_x2(b0, b1, sbase + F_RL + row * 128 + ((chunk ^ s7) << 4));
                mma_bf16(p1c0, p1c1, p1c2, p1c3,
                         afr[ds][0], 0u, afr[ds][2], 0u, b0, b1);
            }
            float a0 = p0c0 + p0c2 + p1c0;
            float a1 = p0c1 + p0c3 + p1c1;
            int h = lane >> 2, kk = k0l + (lane & 3) * 2;
            sc_s[h * 260 + kk]     = (a0 + qkP[half].x) * 0.125f + hvP[half].x;
            sc_s[h * 260 + kk + 1] = (a1 + qkP[half].y) * 0.125f + hvP[half].y;
        }
        __syncthreads();   // scores chunk c ready

        // ---- online softmax partial (warps 0..7, head w) ----
        if (w < 8) {
            float* row = sc_s + w * 260;
            float vals[8];
            float mx = -1e30f;
#pragma unroll
            for (int i = 0; i < 8; i++) { vals[i] = row[i * 32 + lane]; mx = fmaxf(mx, vals[i]); }
#pragma unroll
            for (int o = 16; o; o >>= 1) mx = fmaxf(mx, __shfl_xor_sync(0xffffffffu, mx, o));
            float m_new = (c == 0) ? mx : fmaxf(msm[w], mx);
            float s = 0.f;
#pragma unroll
            for (int i = 0; i < 8; i++) { vals[i] = __expf(vals[i] - m_new); s += vals[i]; }
#pragma unroll
            for (int o = 16; o; o >>= 1) s += __shfl_xor_sync(0xffffffffu, s, o);
#pragma unroll
            for (int i = 0; i < 8; i++) {
                int kk = c * 256 + i * 32 + lane;
                float e = vals[i];
                __nv_bfloat16 eh = __float2bfloat16(e);
                PS[w * 520 + kk] = eh;
                PS[(w + 8) * 520 + kk] = __float2bfloat16(e - __bfloat162float(eh));
            }
            if (lane == 0) {
                if (c == 0) { msm[w] = m_new; ssm[w] = s; }
                else {
                    float f0 = __expf(msm[w] - m_new);
                    float sf = ssm[w] * f0 + s;
                    fsm[w] = f0;
                    ism[w] = 1.f / sf;
                }
            }
        }
        __syncthreads();   // PS chunk + MS state ready

        // ---- stage D chunk c: rescale (c==1) then accumulate ----
        if (c == 1) {
            float f0v = fsm[lane >> 2];
#pragma unroll
            for (int i = 0; i < 4; i++)
#pragma unroll
                for (int j = 0; j < 4; j++) aD[i][j] *= f0v;
        }
#pragma unroll
        for (int ks = 0; ks < 2; ks++) {
            const int k0l = kg * 32 + ks * 16;
            uint32_t af[4];
            uint32_t aaddr = sbase + F_PS + (lane & 15) * 1040
                           + (c * 256 + k0l + ((lane >> 4) << 3)) * 2;
            ldm_x4(af, aaddr);
            const int row = k0l + (lane & 7) + (((lane >> 3) & 1) << 3);
            const int s7 = row & 7;
#pragma unroll
            for (int ntl = 0; ntl < 4; ntl++) {
                int d0 = (ng * 4 + ntl) * 8;
                uint32_t b0, b1;
                ldm_x2_trans(b0, b1, sbase + F_RH + row * 128 + (((d0 >> 3) ^ s7) << 4));
                mma_bf16(aD[ntl][0], aD[ntl][1], aD[ntl][2], aD[ntl][3],
                         af[0], af[1], af[2], af[3], b0, b1);
            }
#pragma unroll
            for (int ntl = 0; ntl < 4; ntl++) {
                int d0 = (ng * 4 + ntl) * 8;
                uint32_t b0, b1;
                ldm_x2_trans(b0, b1, sbase + F_RL + row * 128 + (((d0 >> 3) ^ s7) << 4));
                mma_bf16(aD[ntl][0], aD[ntl][1], aD[ntl][2], aD[ntl][3],
                         af[0], 0u, af[2], 0u, b0, b1);
            }
        }

        if (c == 0) {
            // next chunk LDG (after stage D so regs are free; exposed latency
            // is covered by the co-resident CTA)
            int rr = tid >> 1, f0 = (tid & 1) * 8;
            const float4* src = (const float4*)(rg + (size_t)(256 + rr) * 64) + f0;
#pragma unroll
            for (int j = 0; j < 8; j++) stg[j] = src[j];
        }
        __syncthreads();   // buffer free for next chunk / stage D complete
    }

    // ---- reduce + write out + write probs ----
#pragma unroll
    for (int ntl = 0; ntl < 4; ntl++) {
        int slot = kg * 8 + ng * 4 + ntl;
        *(float2*)&red[(slot * 32 + lane) * 2] =
            make_float2(aD[ntl][0] + aD[ntl][2], aD[ntl][1] + aD[ntl][3]);
    }
    __syncthreads();

    if (w < 8) {
        float rx = 0.f, ry = 0.f;
#pragma unroll
        for (int kgi = 0; kgi < 8; kgi++) {
            float2 s = *(const float2*)&red[((kgi * 8 + w) * 32 + lane) * 2];
            rx += s.x; ry += s.y;
        }
        int h = lane >> 2, d = w * 8 + (lane & 3) * 2;
        float isv = ism[h];
        *(float2*)&out[((size_t)b * 512 + q) * 512 + h * 64 + d] =
            make_float2(rx * isv, ry * isv);

        // normalized probs -> g_ps (split bf16)
        float f0v = fsm[w], isw = ism[w];
        __nv_bfloat16* pgp = g_ps + ((size_t)(b * 8 + w) * 512 + q) * 1024;
#pragma unroll
        for (int i = 0; i < 16; i++) {
            int kk = i * 32 + lane;
            float e = __bfloat162float(PS[w * 520 + kk])
                    + __bfloat162float(PS[(w + 8) * 520 + kk]);
            float p = e * ((kk < 256) ? f0v * isw : isw);
            __nv_bfloat16 ph = __float2bfloat16(p);
            pgp[kk] = ph;
            pgp[512 + kk] = __float2bfloat16(p - __bfloat162float(ph));
        }
    }
}

// =============================================================================
// K4: ctx += probs @ v via mma.sync (unchanged).
// =============================================================================
__global__ __launch_bounds__(256) void k_ctx_mma(float* __restrict__ out)
{
    extern __shared__ char smp[];
    __nv_bfloat16* As = (__nv_bfloat16*)smp;
    __nv_bfloat16* Bs = As + 2 * A_BUF_ELE;

    const int m0 = blockIdx.x * 128;
    const int bh = blockIdx.y;
    const int tbase = blockIdx.z * 12;
    const int b = bh >> 3, h = bh & 7;
    const __nv_bfloat16* Ap = g_ps + (size_t)bh * 512 * 1024;
    const __nv_bfloat16* Bv = g_vT + (size_t)bh * 64 * 1024;

    const int tid = threadIdx.x;
    const int wid = tid >> 5, lane = tid & 31;
    const int wm = wid >> 1, wn = wid & 1;
    const int g  = lane >> 2, tg = lane & 3;

    float acc[2][4][4];
#pragma unroll
    for (int mt = 0; mt < 2; mt++)
#pragma unroll
        for (int nt = 0; nt < 4; nt++)
#pragma unroll
            for (int e = 0; e < 4; e++) acc[mt][nt][e] = 0.f;

    auto aoff = [](int t) { return t < 8 ? t * 64 : t < 16 ? 512 + (t - 8) * 64 : (t - 16) * 64; };
    auto boff = [](int t) { return t < 8 ? t * 64 : t < 16 ? (t - 8) * 64 : 512 + (t - 16) * 64; };

    auto load_chunk = [&](int c, int buf) {
        __nv_bfloat16* Ad = As + buf * A_BUF_ELE;
        __nv_bfloat16* Bd = Bs + buf * B_BUF_ELE;
        int ao = aoff(c), bo = boff(c);
#pragma unroll
        for (int i = 0; i < 4; i++) {
            int flat = i * 256 + tid;
            int row = flat >> 3, seg = flat & 7;
            cp_async16(Ad + row * PADK + seg * 8,
                       Ap + (size_t)(m0 + row) * 1024 + ao + seg * 8);
        }
#pragma unroll
        for (int i = 0; i < 2; i++) {
            int flat = i * 256 + tid;
            int row = flat >> 3, seg = flat & 7;
            cp_async16(Bd + row * PADK + seg * 8,
                       Bv + (size_t)row * 1024 + bo + seg * 8);
        }
        cp_commit();
    };

    load_chunk(tbase, 0);

#pragma unroll 1
    for (int t = 0; t < 12; t++) {
        if (t < 11) load_chunk(tbase + t + 1, (t + 1) & 1);
        if (t < 11) cp_wait<1>(); else cp_wait<0>();
        __syncthreads();

        const __nv_bfloat16* Ab = As + (t & 1) * A_BUF_ELE;
        const __nv_bfloat16* Bb = Bs + (t & 1) * B_BUF_ELE;

#pragma unroll
        for (int ks = 0; ks < 4; ks++) {
            const int kb = ks * 16;
            uint32_t af[2][4], bf[4][2];
#pragma unroll
            for (int mt = 0; mt < 2; mt++) {
                int r0 = wm * 32 + mt * 16 + g;
                af[mt][0] = *(const uint32_t*)&Ab[(r0)      * PADK + kb + tg * 2];
                af[mt][1] = *(const uint32_t*)&Ab[(r0 + 8)  * PADK + kb + tg * 2];
                af[mt][2] = *(const uint32_t*)&Ab[(r0)      * PADK + kb + tg * 2 + 8];
                af[mt][3] = *(const uint32_t*)&Ab[(r0 + 8)  * PADK + kb + tg * 2 + 8];
            }
#pragma unroll
            for (int nt = 0; nt < 4; nt++) {
                int nr = wn * 32 + nt * 8 + g;
                bf[nt][0] = *(const uint32_t*)&Bb[nr * PADK + kb + tg * 2];
                bf[nt][1] = *(const uint32_t*)&Bb[nr * PADK + kb + tg * 2 + 8];
            }
#pragma unroll
            for (int mt = 0; mt < 2; mt++)
#pragma unroll
                for (int nt = 0; nt < 4; nt++)
                    mma_bf16(acc[mt][nt][0], acc[mt][nt][1], acc[mt][nt][2], acc[mt][nt][3],
                             af[mt][0], af[mt][1], af[mt][2], af[mt][3],
                             bf[nt][0], bf[nt][1]);
        }
        __syncthreads();
    }

#pragma unroll
    for (int mt = 0; mt < 2; mt++) {
        int r0 = m0 + wm * 32 + mt * 16 + g;
#pragma unroll
        for (int nt = 0; nt < 4; nt++) {
            int cl = wn * 32 + nt * 8 + tg * 2;
            float* p0 = &out[((size_t)(b * 512 + r0)) * 512 + h * 64 + cl];
            atomicAdd(p0 + 0, acc[mt][nt][0]);
            atomicAdd(p0 + 1, acc[mt][nt][1]);
            float* p1 = &out[((size_t)(b * 512 + r0 + 8)) * 512 + h * 64 + cl];
            atomicAdd(p1 + 0, acc[mt][nt][2]);
            atomicAdd(p1 + 1, acc[mt][nt][3]);
        }
    }
}

// =============================================================================
extern "C" void kernel_launch(void* const* d_in, const int* in_sizes, int n_in,
                              void* d_out, int out_size)
{
    const float* hidden = (const float*)d_in[0];
    const float* heads  = (const float*)d_in[1];
    const float* rels   = (const float*)d_in[2];
    const float* Wq = (const float*)d_in[3];
    const float* bq = (const float*)d_in[4];
    const float* Wk = (const float*)d_in[5];
    const float* bk = (const float*)d_in[6];
    const float* Wv = (const float*)d_in[7];
    const float* bv = (const float*)d_in[8];
    float* out = (float*)d_out;

    k_prep<<<1024, 256>>>(hidden, Wq, Wk, Wv);

    cudaFuncSetAttribute(k_proj_mma, cudaFuncAttributeMaxDynamicSharedMemorySize, SMEM_PROJ);
    dim3 g1(8, 16, 3);
    k_proj_mma<<<g1, 256, SMEM_PROJ>>>(bq, bk, bv);

    cudaFuncSetAttribute(k_scores_mma, cudaFuncAttributeMaxDynamicSharedMemorySize, SMEM_SC2);
    dim3 g2(4, 4, 32);
    k_scores_mma<<<g2, 256, SMEM_SC2>>>();

    cudaFuncSetAttribute(k_fused, cudaFuncAttributeMaxDynamicSharedMemorySize, SMEM_FUSED);
    k_fused<<<2048, 512, SMEM_FUSED>>>(rels, heads, out);

    cudaFuncSetAttribute(k_ctx_mma, cudaFuncAttributeMaxDynamicSharedMemorySize, SMEM_PROJ);
    dim3 g4(4, 32, 2);
    k_ctx_mma<<<g4, 256, SMEM_PROJ>>>(out);
}

// round 17
// speedup vs baseline: 1.4435x; 1.4435x over previous
#include <cuda_runtime.h>
#include <cuda_bf16.h>
#include <cstdint>
#include <cstddef>

#define B_ 4
#define L_ 512
#define HID_ 512
#define H_ 8
#define DH_ 64

// ---------------- scratch (device globals; no allocations allowed) ----------
__device__ float g_sc[B_ * H_ * L_ * L_];            // qk scores (fp32)
__device__ __nv_bfloat16 g_Xs[2048 * 1536];          // proj A split
__device__ __nv_bfloat16 g_Ws[3 * 512 * 1536];       // proj B split
__device__ __nv_bfloat16 g_qs[32 * 512 * 128];       // q split [bh][l][qh|ql]
__device__ __nv_bfloat16 g_ks[32 * 512 * 128];       // k split [bh][l][kh|kl]
__device__ __nv_bfloat16 g_ps[32 * 512 * 1024];      // probs split [bh][q][ph|pl]
__device__ __nv_bfloat16 g_vT[32 * 64 * 1024];       // v^T split [bh][d][vh|vl]

// ---------------- cp.async helpers ------------------------------------------
__device__ __forceinline__ void cp_async16(void* smem, const void* gmem) {
    unsigned s = (unsigned)__cvta_generic_to_shared(smem);
    asm volatile("cp.async.cg.shared.global [%0], [%1], 16;\n" :: "r"(s), "l"(gmem));
}
__device__ __forceinline__ void cp_commit() {
    asm volatile("cp.async.commit_group;\n");
}
template <int N>
__device__ __forceinline__ void cp_wait() {
    asm volatile("cp.async.wait_group %0;\n" :: "n"(N));
}

// ---------------- warp mma / ldmatrix (sm_80+, no 'a' feature) ---------------
__device__ __forceinline__ void mma_bf16(float& c0, float& c1, float& c2, float& c3,
                                         uint32_t a0, uint32_t a1, uint32_t a2, uint32_t a3,
                                         uint32_t b0, uint32_t b1) {
    asm volatile(
        "mma.sync.aligned.m16n8k16.row.col.f32.bf16.bf16.f32 "
        "{%0,%1,%2,%3}, {%4,%5,%6,%7}, {%8,%9}, {%0,%1,%2,%3};"
        : "+f"(c0), "+f"(c1), "+f"(c2), "+f"(c3)
        : "r"(a0), "r"(a1), "r"(a2), "r"(a3), "r"(b0), "r"(b1));
}
__device__ __forceinline__ void ldm_x4(uint32_t* r, uint32_t addr) {
    asm volatile("ldmatrix.sync.aligned.m8n8.x4.shared.b16 {%0,%1,%2,%3}, [%4];"
                 : "=r"(r[0]), "=r"(r[1]), "=r"(r[2]), "=r"(r[3]) : "r"(addr));
}
__device__ __forceinline__ void ldm_x2(uint32_t& r0, uint32_t& r1, uint32_t addr) {
    asm volatile("ldmatrix.sync.aligned.m8n8.x2.shared.b16 {%0,%1}, [%2];"
                 : "=r"(r0), "=r"(r1) : "r"(addr));
}
__device__ __forceinline__ void ldm_x2_trans(uint32_t& r0, uint32_t& r1, uint32_t addr) {
    asm volatile("ldmatrix.sync.aligned.m8n8.x2.trans.shared.b16 {%0,%1}, [%2];"
                 : "=r"(r0), "=r"(r1) : "r"(addr));
}
__device__ __forceinline__ uint32_t cvt_bf16x2(float a, float b) {
    uint32_t w;
    asm("cvt.rn.bf16x2.f32 %0, %1, %2;" : "=r"(w) : "f"(b), "f"(a));
    return w;
}

// =============================================================================
// K0: build split-bf16 operands for the projection, K=1536.
// =============================================================================
__global__ __launch_bounds__(256) void k_prep(
    const float* __restrict__ X,
    const float* __restrict__ Wq, const float* __restrict__ Wk,
    const float* __restrict__ Wv)
{
    const int stride = gridDim.x * blockDim.x;
    for (int i = blockIdx.x * blockDim.x + threadIdx.x; i < 2048 * 512; i += stride) {
        int m = i >> 9, k = i & 511;
        float x = X[i];
        __nv_bfloat16 hi = __float2bfloat16(x);
        __nv_bfloat16 lo = __float2bfloat16(x - __bfloat162float(hi));
        __nv_bfloat16* row = g_Xs + (size_t)m * 1536;
        row[k] = hi; row[512 + k] = lo; row[1024 + k] = hi;
    }
    for (int i = blockIdx.x * blockDim.x + threadIdx.x; i < 3 * 512 * 512; i += stride) {
        int z = i >> 18;
        int r = i & 262143;
        const float* W = (z == 0) ? Wq : (z == 1) ? Wk : Wv;
        int n = r >> 9, k = r & 511;
        float x = W[r];
        __nv_bfloat16 hi = __float2bfloat16(x);
        __nv_bfloat16 lo = __float2bfloat16(x - __bfloat162float(hi));
        __nv_bfloat16* row = g_Ws + (size_t)z * 512 * 1536 + (size_t)n * 1536;
        row[k] = hi; row[512 + k] = hi; row[1024 + k] = lo;
    }
}

// =============================================================================
// K1: QKV projection via mma.sync (unchanged from R15).
// =============================================================================
#define PADK 72
#define A_BUF_ELE (128 * PADK)
#define B_BUF_ELE (64 * PADK)
#define SMEM_PROJ ((2 * A_BUF_ELE + 2 * B_BUF_ELE) * 2 + 64 * 4)

__global__ __launch_bounds__(256) void k_proj_mma(
    const float* __restrict__ bq, const float* __restrict__ bk,
    const float* __restrict__ bv)
{
    extern __shared__ char smp[];
    __nv_bfloat16* As = (__nv_bfloat16*)smp;
    __nv_bfloat16* Bs = As + 2 * A_BUF_ELE;
    float* biasS = (float*)(Bs + 2 * B_BUF_ELE);

    const int n0 = blockIdx.x * 64;
    const int m0 = blockIdx.y * 128;
    const int z  = blockIdx.z;
    const float* bias = (z == 0) ? bq : (z == 1) ? bk : bv;
    const __nv_bfloat16* Wz = g_Ws + (size_t)z * 512 * 1536;

    const int tid = threadIdx.x;
    const int wid = tid >> 5, lane = tid & 31;
    const int wm = wid >> 1, wn = wid & 1;
    const int g  = lane >> 2, tg = lane & 3;

    if (tid < 64) biasS[tid] = bias[n0 + tid];

    float acc[2][4][4];
#pragma unroll
    for (int mt = 0; mt < 2; mt++)
#pragma unroll
        for (int nt = 0; nt < 4; nt++)
#pragma unroll
            for (int e = 0; e < 4; e++) acc[mt][nt][e] = 0.f;

    auto load_chunk = [&](int c, int buf) {
        __nv_bfloat16* Ad = As + buf * A_BUF_ELE;
        __nv_bfloat16* Bd = Bs + buf * B_BUF_ELE;
#pragma unroll
        for (int i = 0; i < 4; i++) {
            int flat = i * 256 + tid;
            int row = flat >> 3, seg = flat & 7;
            cp_async16(Ad + row * PADK + seg * 8,
                       g_Xs + (size_t)(m0 + row) * 1536 + c * 64 + seg * 8);
        }
#pragma unroll
        for (int i = 0; i < 2; i++) {
            int flat = i * 256 + tid;
            int row = flat >> 3, seg = flat & 7;
            cp_async16(Bd + row * PADK + seg * 8,
                       Wz + (size_t)(n0 + row) * 1536 + c * 64 + seg * 8);
        }
        cp_commit();
    };

    load_chunk(0, 0);

#pragma unroll 1
    for (int t = 0; t < 24; t++) {
        if (t < 23) load_chunk(t + 1, (t + 1) & 1);
        if (t < 23) cp_wait<1>(); else cp_wait<0>();
        __syncthreads();

        const __nv_bfloat16* Ab = As + (t & 1) * A_BUF_ELE;
        const __nv_bfloat16* Bb = Bs + (t & 1) * B_BUF_ELE;

#pragma unroll
        for (int ks = 0; ks < 4; ks++) {
            const int kb = ks * 16;
            uint32_t af[2][4], bf[4][2];
#pragma unroll
            for (int mt = 0; mt < 2; mt++) {
                int r0 = wm * 32 + mt * 16 + g;
                af[mt][0] = *(const uint32_t*)&Ab[(r0)      * PADK + kb + tg * 2];
                af[mt][1] = *(const uint32_t*)&Ab[(r0 + 8)  * PADK + kb + tg * 2];
                af[mt][2] = *(const uint32_t*)&Ab[(r0)      * PADK + kb + tg * 2 + 8];
                af[mt][3] = *(const uint32_t*)&Ab[(r0 + 8)  * PADK + kb + tg * 2 + 8];
            }
#pragma unroll
            for (int nt = 0; nt < 4; nt++) {
                int nr = wn * 32 + nt * 8 + g;
                bf[nt][0] = *(const uint32_t*)&Bb[nr * PADK + kb + tg * 2];
                bf[nt][1] = *(const uint32_t*)&Bb[nr * PADK + kb + tg * 2 + 8];
            }
#pragma unroll
            for (int mt = 0; mt < 2; mt++)
#pragma unroll
                for (int nt = 0; nt < 4; nt++)
                    mma_bf16(acc[mt][nt][0], acc[mt][nt][1], acc[mt][nt][2], acc[mt][nt][3],
                             af[mt][0], af[mt][1], af[mt][2], af[mt][3],
                             bf[nt][0], bf[nt][1]);
        }
        __syncthreads();
    }

    const int hh = n0 >> 6;

    if (z == 2) {
        float* vts = (float*)smp;
#pragma unroll
        for (int mt = 0; mt < 2; mt++) {
            int rl = wm * 32 + mt * 16 + g;
#pragma unroll
            for (int nt = 0; nt < 4; nt++) {
                int cl = wn * 32 + nt * 8 + tg * 2;
                vts[rl * 68 + cl]           = acc[mt][nt][0] + biasS[cl];
                vts[rl * 68 + cl + 1]       = acc[mt][nt][1] + biasS[cl + 1];
                vts[(rl + 8) * 68 + cl]     = acc[mt][nt][2] + biasS[cl];
                vts[(rl + 8) * 68 + cl + 1] = acc[mt][nt][3] + biasS[cl + 1];
            }
        }
        __syncthreads();
        const int d = tid & 63, ksb = tid >> 6;
        const int bh = (m0 >> 9) * 8 + hh;
        const int l0 = (m0 & 511) + ksb * 32;
        __nv_bfloat16* dst = g_vT + ((size_t)bh * 64 + d) * 1024 + l0;
#pragma unroll
        for (int seg = 0; seg < 4; seg++) {
            union { __nv_bfloat16 bb[8]; uint4 u; } hu, lu;
#pragma unroll
            for (int j = 0; j < 8; j++) {
                float x = vts[(ksb * 32 + seg * 8 + j) * 68 + d];
                __nv_bfloat16 hb = __float2bfloat16(x);
                hu.bb[j] = hb;
                lu.bb[j] = __float2bfloat16(x - __bfloat162float(hb));
            }
            *(uint4*)(dst + seg * 8)       = hu.u;
            *(uint4*)(dst + 512 + seg * 8) = lu.u;
        }
    } else {
        __nv_bfloat16* QK = (z == 0) ? g_qs : g_ks;
#pragma unroll
        for (int mt = 0; mt < 2; mt++) {
            int r0 = m0 + wm * 32 + mt * 16 + g;
#pragma unroll
            for (int nt = 0; nt < 4; nt++) {
                int cl = wn * 32 + nt * 8 + tg * 2;
                float x00 = acc[mt][nt][0] + biasS[cl];
                float x01 = acc[mt][nt][1] + biasS[cl + 1];
                float x10 = acc[mt][nt][2] + biasS[cl];
                float x11 = acc[mt][nt][3] + biasS[cl + 1];
                int b0 = r0 >> 9, l0 = r0 & 511;
                int b1 = (r0 + 8) >> 9, l1 = (r0 + 8) & 511;
                __nv_bfloat16* d0 = QK + ((size_t)(b0 * 8 + hh) * 512 + l0) * 128 + cl;
                __nv_bfloat16* d1 = QK + ((size_t)(b1 * 8 + hh) * 512 + l1) * 128 + cl;
                __nv_bfloat16 h00 = __float2bfloat16(x00), h01 = __float2bfloat16(x01);
                __nv_bfloat16 h10 = __float2bfloat16(x10), h11 = __float2bfloat16(x11);
                *(uint32_t*)d0 = ((uint32_t)__bfloat16_as_ushort(h01) << 16)
                               | __bfloat16_as_ushort(h00);
                *(uint32_t*)d1 = ((uint32_t)__bfloat16_as_ushort(h11) << 16)
                               | __bfloat16_as_ushort(h10);
                *(uint32_t*)(d0 + 64) = cvt_bf16x2(x00 - __bfloat162float(h00),
                                                   x01 - __bfloat162float(h01));
                *(uint32_t*)(d1 + 64) = cvt_bf16x2(x10 - __bfloat162float(h10),
                                                   x11 - __bfloat162float(h11));
            }
        }
    }
}

// =============================================================================
// K2: scores via mma.sync, single-phase (unchanged from R15).
// =============================================================================
#define SC_TILE (128 * PADK)
#define SMEM_SC2 (6 * SC_TILE * 2)

__global__ __launch_bounds__(256) void k_scores_mma()
{
    extern __shared__ char smp[];
    __nv_bfloat16* As = (__nv_bfloat16*)smp;
    __nv_bfloat16* Bs = As + 3 * SC_TILE;

    const int n0 = blockIdx.x * 128;
    const int m0 = blockIdx.y * 128;
    const int bh = blockIdx.z;
    const __nv_bfloat16* Aq = g_qs + (size_t)bh * 512 * 128;
    const __nv_bfloat16* Bk = g_ks + (size_t)bh * 512 * 128;
    float* C = g_sc + (size_t)bh * 262144;

    const int tid = threadIdx.x;
    const int wid = tid >> 5, lane = tid & 31;
    const int wm = wid >> 1, wn = wid & 1;
    const int g  = lane >> 2, tg = lane & 3;

    const int Aoff[3] = { 0, 64, 0 };
    const int Boff[3] = { 0, 0, 64 };

#pragma unroll
    for (int c = 0; c < 3; c++) {
#pragma unroll
        for (int i = 0; i < 4; i++) {
            int flat = i * 256 + tid;
            int row = flat >> 3, seg = flat & 7;
            cp_async16(As + c * SC_TILE + row * PADK + seg * 8,
                       Aq + (size_t)(m0 + row) * 128 + Aoff[c] + seg * 8);
        }
#pragma unroll
        for (int i = 0; i < 4; i++) {
            int flat = i * 256 + tid;
            int row = flat >> 3, seg = flat & 7;
            cp_async16(Bs + c * SC_TILE + row * PADK + seg * 8,
                       Bk + (size_t)(n0 + row) * 128 + Boff[c] + seg * 8);
        }
    }
    cp_commit();
    cp_wait<0>();
    __syncthreads();

    float acc[2][8][4];
#pragma unroll
    for (int mt = 0; mt < 2; mt++)
#pragma unroll
        for (int nt = 0; nt < 8; nt++)
#pragma unroll
            for (int e = 0; e < 4; e++) acc[mt][nt][e] = 0.f;

#pragma unroll
    for (int c = 0; c < 3; c++) {
        const __nv_bfloat16* Ab = As + c * SC_TILE;
        const __nv_bfloat16* Bb = Bs + c * SC_TILE;
#pragma unroll
        for (int ks = 0; ks < 4; ks++) {
            const int kb = ks * 16;
            uint32_t af[2][4], bf[8][2];
#pragma unroll
            for (int mt = 0; mt < 2; mt++) {
                int r0 = wm * 32 + mt * 16 + g;
                af[mt][0] = *(const uint32_t*)&Ab[(r0)      * PADK + kb + tg * 2];
                af[mt][1] = *(const uint32_t*)&Ab[(r0 + 8)  * PADK + kb + tg * 2];
                af[mt][2] = *(const uint32_t*)&Ab[(r0)      * PADK + kb + tg * 2 + 8];
                af[mt][3] = *(const uint32_t*)&Ab[(r0 + 8)  * PADK + kb + tg * 2 + 8];
            }
#pragma unroll
            for (int nt = 0; nt < 8; nt++) {
                int nr = wn * 64 + nt * 8 + g;
                bf[nt][0] = *(const uint32_t*)&Bb[nr * PADK + kb + tg * 2];
                bf[nt][1] = *(const uint32_t*)&Bb[nr * PADK + kb + tg * 2 + 8];
            }
#pragma unroll
            for (int mt = 0; mt < 2; mt++)
#pragma unroll
                for (int nt = 0; nt < 8; nt++)
                    mma_bf16(acc[mt][nt][0], acc[mt][nt][1], acc[mt][nt][2], acc[mt][nt][3],
                             af[mt][0], af[mt][1], af[mt][2], af[mt][3],
                             bf[nt][0], bf[nt][1]);
        }
    }

#pragma unroll
    for (int mt = 0; mt < 2; mt++) {
        int r0 = m0 + wm * 32 + mt * 16 + g;
#pragma unroll
        for (int nt = 0; nt < 8; nt++) {
            int cl = wn * 64 + nt * 8 + tg * 2;
            *(float2*)&C[(size_t)r0 * 512 + n0 + cl] =
                make_float2(acc[mt][nt][0], acc[mt][nt][1]);
            *(float2*)&C[(size_t)(r0 + 8) * 512 + n0 + cl] =
                make_float2(acc[mt][nt][2], acc[mt][nt][3]);
        }
    }
}

// =============================================================================
// K3: fused — flash-chunked v2: 4 chunks of 128 rows, cp.async raw staging
// (NO register staging -> no spills), online softmax, 2 CTAs/SM.
// =============================================================================
#define F_RAW 0                       // fp32 [128][68] = 34816
#define F_RH 34816                    // 16384
#define F_RL 51200                    // 16384
#define F_SC 67584                    // float [8][132] = 4224
#define F_QS 71808                    // bf16 [16][136] = 4352
#define F_PS 76160                    // bf16 [16][520] = 16640
#define F_RED 92800                   // float2 [64][32] = 16384
#define F_MS 109184                   // m[8] s[8] fsm[32] ism[8] = 224
#define SMEM_FUSED 109440

__global__ __launch_bounds__(512, 2) void k_fused(
    const float* __restrict__ rels,
    const float* __restrict__ heads,
    float* __restrict__ out)
{
    extern __shared__ char smf[];
    const uint32_t sbase = (uint32_t)__cvta_generic_to_shared(smf);
    float* raw  = (float*)(smf + F_RAW);
    float* sc_s = (float*)(smf + F_SC);
    __nv_bfloat16* QS = (__nv_bfloat16*)(smf + F_QS);
    __nv_bfloat16* PS = (__nv_bfloat16*)(smf + F_PS);
    float* red = (float*)(smf + F_RED);
    float* msm = (float*)(smf + F_MS);        // [8]
    float* ssm = msm + 8;                     // [8]
    float* fsm = msm + 16;                    // [4][8]
    float* ism = msm + 48;                    // [8]

    const int bq = blockIdx.x;
    const int b = bq >> 9, q = bq & 511;
    const int tid = threadIdx.x;
    const int lane = tid & 31, w = tid >> 5;

    const float* rg = rels + (size_t)bq * (512 * 64);
    const size_t hoff = ((size_t)b * 512 + q) * 512;

    const int rr = tid >> 2;            // 0..127 local row
    const int fs = (tid & 3) * 16;      // float seg base
    const int c0 = (tid & 3) * 2;       // 16B-chunk base
    const int s7 = rr & 7;

    auto issue_raw = [&](int c) {
        const float* src = rg + (size_t)(c * 128 + rr) * 64 + fs;
        float* dst = raw + rr * 68 + fs;
        cp_async16(dst, src);
        cp_async16(dst + 4, src + 4);
        cp_async16(dst + 8, src + 8);
        cp_async16(dst + 12, src + 12);
        cp_commit();
    };

    // ---- prologue ----
    issue_raw(0);
    if (tid < 128) {
        int h = tid >> 4, dq = tid & 15;
        const __nv_bfloat16* src = g_qs + ((size_t)(b * 8 + h) * 512 + q) * 128 + dq * 4;
        *(uint2*)&QS[h * 136 + dq * 4]       = *(const uint2*)src;
        *(uint2*)&QS[(h + 8) * 136 + dq * 4] = *(const uint2*)(src + 64);
    }

    // qk/heads prefetch: 1 tile per warp per chunk
    float2 qkP[4], hvP[4];
    {
        int hh = lane >> 2;
#pragma unroll
        for (int c = 0; c < 4; c++) {
            int kkg = c * 128 + w * 8 + (lane & 3) * 2;
            qkP[c] = *(const float2*)&g_sc[(size_t)(b * 8 + hh) * 262144
                                           + (size_t)q * 512 + kkg];
            hvP[c] = *(const float2*)&heads[hoff + kkg];
        }
    }
    __syncthreads();    // QS ready

    uint32_t afr[4][4];
#pragma unroll
    for (int ds = 0; ds < 4; ds++) {
        uint32_t addr = sbase + F_QS + (lane & 15) * 272
                      + (ds * 16 + ((lane >> 4) << 3)) * 2;
        ldm_x4(afr[ds], addr);
    }

    float aD[4][4];
#pragma unroll
    for (int i = 0; i < 4; i++)
#pragma unroll
        for (int j = 0; j < 4; j++) aD[i][j] = 0.f;
    const int kg = w >> 1, ng = w & 1;

#pragma unroll 1
    for (int c = 0; c < 4; c++) {
        cp_wait<0>();
        __syncthreads();   // raw chunk c ready; RH/RL free (stage D of c-1 done)

        // ---- convert raw -> RH/RL (16 floats/thread, from smem) ----
        {
            char* rhrow = smf + F_RH + rr * 128;
            char* rlrow = smf + F_RL + rr * 128;
            const float* src = raw + rr * 68 + fs;
#pragma unroll
            for (int jj = 0; jj < 2; jj++) {
                uint32_t hw[4], lw[4];
#pragma unroll
                for (int j = 0; j < 4; j++) {
                    float x0 = src[jj * 8 + 2 * j], x1 = src[jj * 8 + 2 * j + 1];
                    uint32_t u0 = __float_as_uint(x0), u1 = __float_as_uint(x1);
                    hw[j] = __byte_perm(u0, u1, 0x7632);
                    float h0f = __uint_as_float(u0 & 0xFFFF0000u);
                    float h1f = __uint_as_float(u1 & 0xFFFF0000u);
                    lw[j] = cvt_bf16x2(x0 - h0f, x1 - h1f);
                }
                int chunk = c0 + jj;
                *(uint4*)(rhrow + ((chunk ^ s7) << 4)) = make_uint4(hw[0], hw[1], hw[2], hw[3]);
                *(uint4*)(rlrow + ((chunk ^ s7) << 4)) = make_uint4(lw[0], lw[1], lw[2], lw[3]);
            }
        }
        __syncthreads();   // RH/RL ready; raw free

        if (c < 3) issue_raw(c + 1);   // overlaps with everything below

        // ---- stage B: 16 warps x 1 n-tile (local rows 0..127) ----
        {
            const int k0l = w * 8;
            float p0c0 = 0.f, p0c1 = 0.f, p0c2 = 0.f, p0c3 = 0.f;
            float p1c0 = 0.f, p1c1 = 0.f, p1c2 = 0.f, p1c3 = 0.f;
            const int row = k0l + (lane & 7);
            const int rs7 = row & 7;
            const int csel = (lane >> 3) & 1;
#pragma unroll
            for (int ds = 0; ds < 4; ds++) {
                int chunk = ds * 2 + csel;
                uint32_t b0, b1;
                ldm_x2(b0, b1, sbase + F_RH + row * 128 + ((chunk ^ rs7) << 4));
                mma_bf16(p0c0, p0c1, p0c2, p0c3,
                         afr[ds][0], afr[ds][1], afr[ds][2], afr[ds][3], b0, b1);
            }
#pragma unroll
            for (int ds = 0; ds < 4; ds++) {
                int chunk = ds * 2 + csel;
                uint32_t b0, b1;
                ldm_x2(b0, b1, sbase + F_RL + row * 128 + ((chunk ^ rs7) << 4));
                mma_bf16(p1c0, p1c1, p1c2, p1c3,
                         afr[ds][0], 0u, afr[ds][2], 0u, b0, b1);
            }
            float a0 = p0c0 + p0c2 + p1c0;
            float a1 = p0c1 + p0c3 + p1c1;
            int h = lane >> 2, kk = k0l + (lane & 3) * 2;
            sc_s[h * 132 + kk]     = (a0 + qkP[c].x) * 0.125f + hvP[c].x;
            sc_s[h * 132 + kk + 1] = (a1 + qkP[c].y) * 0.125f + hvP[c].y;
        }
        __syncthreads();   // scores chunk c ready

        // ---- online softmax partial (warps 0..7, head w) ----
        if (w < 8) {
            float* row = sc_s + w * 132;
            float vals[4];
            float mx = -1e30f;
#pragma unroll
            for (int i = 0; i < 4; i++) { vals[i] = row[i * 32 + lane]; mx = fmaxf(mx, vals[i]); }
#pragma unroll
            for (int o = 16; o; o >>= 1) mx = fmaxf(mx, __shfl_xor_sync(0xffffffffu, mx, o));
            float m_new = (c == 0) ? mx : fmaxf(msm[w], mx);
            float s = 0.f;
#pragma unroll
            for (int i = 0; i < 4; i++) { vals[i] = __expf(vals[i] - m_new); s += vals[i]; }
#pragma unroll
            for (int o = 16; o; o >>= 1) s += __shfl_xor_sync(0xffffffffu, s, o);
#pragma unroll
            for (int i = 0; i < 4; i++) {
                int kk = c * 128 + i * 32 + lane;
                float e = vals[i];
                __nv_bfloat16 eh = __float2bfloat16(e);
                PS[w * 520 + kk] = eh;
                PS[(w + 8) * 520 + kk] = __float2bfloat16(e - __bfloat162float(eh));
            }
            if (lane == 0) {
                float f = (c == 0) ? 1.f : __expf(msm[w] - m_new);
                ssm[w] = (c == 0) ? s : ssm[w] * f + s;
                msm[w] = m_new;
                fsm[c * 8 + w] = f;
                if (c == 3) ism[w] = 1.f / ssm[w];
            }
        }
        __syncthreads();   // PS chunk + MS state ready

        // ---- stage D chunk c: rescale then accumulate ----
        if (c > 0) {
            float f0v = fsm[c * 8 + (lane >> 2)];
#pragma unroll
            for (int i = 0; i < 4; i++)
#pragma unroll
                for (int j = 0; j < 4; j++) aD[i][j] *= f0v;
        }
        {
            const int k0l = kg * 16;
            uint32_t af[4];
            uint32_t aaddr = sbase + F_PS + (lane & 15) * 1040
                           + (c * 128 + k0l + ((lane >> 4) << 3)) * 2;
            ldm_x4(af, aaddr);
            const int row = k0l + (lane & 7) + (((lane >> 3) & 1) << 3);
            const int rs7 = row & 7;
#pragma unroll
            for (int ntl = 0; ntl < 4; ntl++) {
                int d0 = (ng * 4 + ntl) * 8;
                uint32_t b0, b1;
                ldm_x2_trans(b0, b1, sbase + F_RH + row * 128 + (((d0 >> 3) ^ rs7) << 4));
                mma_bf16(aD[ntl][0], aD[ntl][1], aD[ntl][2], aD[ntl][3],
                         af[0], af[1], af[2], af[3], b0, b1);
            }
#pragma unroll
            for (int ntl = 0; ntl < 4; ntl++) {
                int d0 = (ng * 4 + ntl) * 8;
                uint32_t b0, b1;
                ldm_x2_trans(b0, b1, sbase + F_RL + row * 128 + (((d0 >> 3) ^ rs7) << 4));
                mma_bf16(aD[ntl][0], aD[ntl][1], aD[ntl][2], aD[ntl][3],
                         af[0], 0u, af[2], 0u, b0, b1);
            }
        }
        // loop-top sync doubles as "stage D done, RH/RL reusable"
    }

    // ---- reduce + write out + write probs ----
#pragma unroll
    for (int ntl = 0; ntl < 4; ntl++) {
        int slot = kg * 8 + ng * 4 + ntl;
        *(float2*)&red[(slot * 32 + lane) * 2] =
            make_float2(aD[ntl][0] + aD[ntl][2], aD[ntl][1] + aD[ntl][3]);
    }
    __syncthreads();

    if (w < 8) {
        float rx = 0.f, ry = 0.f;
#pragma unroll
        for (int kgi = 0; kgi < 8; kgi++) {
            float2 s = *(const float2*)&red[((kgi * 8 + w) * 32 + lane) * 2];
            rx += s.x; ry += s.y;
        }
        int h = lane >> 2, d = w * 8 + (lane & 3) * 2;
        float isv = ism[h];
        *(float2*)&out[((size_t)b * 512 + q) * 512 + h * 64 + d] =
            make_float2(rx * isv, ry * isv);

        // per-chunk normalization weights (suffix products of f)
        float pw[4];
        pw[3] = ism[w];
        pw[2] = fsm[3 * 8 + w] * pw[3];
        pw[1] = fsm[2 * 8 + w] * pw[2];
        pw[0] = fsm[1 * 8 + w] * pw[1];

        __nv_bfloat16* pgp = g_ps + ((size_t)(b * 8 + w) * 512 + q) * 1024;
#pragma unroll
        for (int i = 0; i < 16; i++) {
            int kk = i * 32 + lane;
            float e = __bfloat162float(PS[w * 520 + kk])
                    + __bfloat162float(PS[(w + 8) * 520 + kk]);
            float p = e * pw[kk >> 7];
            __nv_bfloat16 ph = __float2bfloat16(p);
            pgp[kk] = ph;
            pgp[512 + kk] = __float2bfloat16(p - __bfloat162float(ph));
        }
    }
}

// =============================================================================
// K4: ctx += probs @ v via mma.sync (unchanged).
// =============================================================================
__global__ __launch_bounds__(256) void k_ctx_mma(float* __restrict__ out)
{
    extern __shared__ char smp[];
    __nv_bfloat16* As = (__nv_bfloat16*)smp;
    __nv_bfloat16* Bs = As + 2 * A_BUF_ELE;

    const int m0 = blockIdx.x * 128;
    const int bh = blockIdx.y;
    const int tbase = blockIdx.z * 12;
    const int b = bh >> 3, h = bh & 7;
    const __nv_bfloat16* Ap = g_ps + (size_t)bh * 512 * 1024;
    const __nv_bfloat16* Bv = g_vT + (size_t)bh * 64 * 1024;

    const int tid = threadIdx.x;
    const int wid = tid >> 5, lane = tid & 31;
    const int wm = wid >> 1, wn = wid & 1;
    const int g  = lane >> 2, tg = lane & 3;

    float acc[2][4][4];
#pragma unroll
    for (int mt = 0; mt < 2; mt++)
#pragma unroll
        for (int nt = 0; nt < 4; nt++)
#pragma unroll
            for (int e = 0; e < 4; e++) acc[mt][nt][e] = 0.f;

    auto aoff = [](int t) { return t < 8 ? t * 64 : t < 16 ? 512 + (t - 8) * 64 : (t - 16) * 64; };
    auto boff = [](int t) { return t < 8 ? t * 64 : t < 16 ? (t - 8) * 64 : 512 + (t - 16) * 64; };

    auto load_chunk = [&](int c, int buf) {
        __nv_bfloat16* Ad = As + buf * A_BUF_ELE;
        __nv_bfloat16* Bd = Bs + buf * B_BUF_ELE;
        int ao = aoff(c), bo = boff(c);
#pragma unroll
        for (int i = 0; i < 4; i++) {
            int flat = i * 256 + tid;
            int row = flat >> 3, seg = flat & 7;
            cp_async16(Ad + row * PADK + seg * 8,
                       Ap + (size_t)(m0 + row) * 1024 + ao + seg * 8);
        }
#pragma unroll
        for (int i = 0; i < 2; i++) {
            int flat = i * 256 + tid;
            int row = flat >> 3, seg = flat & 7;
            cp_async16(Bd + row * PADK + seg * 8,
                       Bv + (size_t)row * 1024 + bo + seg * 8);
        }
        cp_commit();
    };

    load_chunk(tbase, 0);

#pragma unroll 1
    for (int t = 0; t < 12; t++) {
        if (t < 11) load_chunk(tbase + t + 1, (t + 1) & 1);
        if (t < 11) cp_wait<1>(); else cp_wait<0>();
        __syncthreads();

        const __nv_bfloat16* Ab = As + (t & 1) * A_BUF_ELE;
        const __nv_bfloat16* Bb = Bs + (t & 1) * B_BUF_ELE;

#pragma unroll
        for (int ks = 0; ks < 4; ks++) {
            const int kb = ks * 16;
            uint32_t af[2][4], bf[4][2];
#pragma unroll
            for (int mt = 0; mt < 2; mt++) {
                int r0 = wm * 32 + mt * 16 + g;
                af[mt][0] = *(const uint32_t*)&Ab[(r0)      * PADK + kb + tg * 2];
                af[mt][1] = *(const uint32_t*)&Ab[(r0 + 8)  * PADK + kb + tg * 2];
                af[mt][2] = *(const uint32_t*)&Ab[(r0)      * PADK + kb + tg * 2 + 8];
                af[mt][3] = *(const uint32_t*)&Ab[(r0 + 8)  * PADK + kb + tg * 2 + 8];
            }
#pragma unroll
            for (int nt = 0; nt < 4; nt++) {
                int nr = wn * 32 + nt * 8 + g;
                bf[nt][0] = *(const uint32_t*)&Bb[nr * PADK + kb + tg * 2];
                bf[nt][1] = *(const uint32_t*)&Bb[nr * PADK + kb + tg * 2 + 8];
            }
#pragma unroll
            for (int mt = 0; mt < 2; mt++)
#pragma unroll
                for (int nt = 0; nt < 4; nt++)
                    mma_bf16(acc[mt][nt][0], acc[mt][nt][1], acc[mt][nt][2], acc[mt][nt][3],
                             af[mt][0], af[mt][1], af[mt][2], af[mt][3],
                             bf[nt][0], bf[nt][1]);
        }
        __syncthreads();
    }

#pragma unroll
    for (int mt = 0; mt < 2; mt++) {
        int r0 = m0 + wm * 32 + mt * 16 + g;
#pragma unroll
        for (int nt = 0; nt < 4; nt++) {
            int cl = wn * 32 + nt * 8 + tg * 2;
            float* p0 = &out[((size_t)(b * 512 + r0)) * 512 + h * 64 + cl];
            atomicAdd(p0 + 0, acc[mt][nt][0]);
            atomicAdd(p0 + 1, acc[mt][nt][1]);
            float* p1 = &out[((size_t)(b * 512 + r0 + 8)) * 512 + h * 64 + cl];
            atomicAdd(p1 + 0, acc[mt][nt][2]);
            atomicAdd(p1 + 1, acc[mt][nt][3]);
        }
    }
}

// =============================================================================
extern "C" void kernel_launch(void* const* d_in, const int* in_sizes, int n_in,
                              void* d_out, int out_size)
{
    const float* hidden = (const float*)d_in[0];
    const float* heads  = (const float*)d_in[1];
    const float* rels   = (const float*)d_in[2];
    const float* Wq = (const float*)d_in[3];
    const float* bq = (const float*)d_in[4];
    const float* Wk = (const float*)d_in[5];
    const float* bk = (const float*)d_in[6];
    const float* Wv = (const float*)d_in[7];
    const float* bv = (const float*)d_in[8];
    float* out = (float*)d_out;

    k_prep<<<1024, 256>>>(hidden, Wq, Wk, Wv);

    cudaFuncSetAttribute(k_proj_mma, cudaFuncAttributeMaxDynamicSharedMemorySize, SMEM_PROJ);
    dim3 g1(8, 16, 3);
    k_proj_mma<<<g1, 256, SMEM_PROJ>>>(bq, bk, bv);

    cudaFuncSetAttribute(k_scores_mma, cudaFuncAttributeMaxDynamicSharedMemorySize, SMEM_SC2);
    dim3 g2(4, 4, 32);
    k_scores_mma<<<g2, 256, SMEM_SC2>>>();

    cudaFuncSetAttribute(k_fused, cudaFuncAttributeMaxDynamicSharedMemorySize, SMEM_FUSED);
    k_fused<<<2048, 512, SMEM_FUSED>>>(rels, heads, out);

    cudaFuncSetAttribute(k_ctx_mma, cudaFuncAttributeMaxDynamicSharedMemorySize, SMEM_PROJ);
    dim3 g4(4, 32, 2);
    k_ctx_mma<<<g4, 256, SMEM_PROJ>>>(out);
}